// round 2
// baseline (speedup 1.0000x reference)
#include <cuda_runtime.h>
#include <cuda_bf16.h>

// Problem constants
#define RR 8
#define NN 40000
#define FF 128           // F_IN == F_OUT == 128
#define EE 160000
#define NEDGES (RR * EE) // 1,280,000

// Scratch (no allocations allowed): y = ent_mat @ weight_ent, and alpha[R]
__device__ float g_y[NN * FF];
__device__ float g_alpha[RR];

// ---------------------------------------------------------------------------
// Kernel 1: alpha[r] = sigmoid( tanh(rel_mat[r,:] @ W1 + b1) @ W2 )
// 1 block, 128 threads. Tiny.
// ---------------------------------------------------------------------------
__global__ void alpha_kernel(const float* __restrict__ rel_mat,
                             const float* __restrict__ w1,
                             const float* __restrict__ b1,
                             const float* __restrict__ w2) {
    __shared__ float h[RR][FF];
    int o = threadIdx.x;  // 0..127
    float bo = b1[o];
    float w2o = w2[o];
#pragma unroll
    for (int r = 0; r < RR; r++) {
        float acc = bo;
        for (int f = 0; f < FF; f++) {
            acc += rel_mat[r * FF + f] * w1[f * FF + o];
        }
        h[r][o] = tanhf(acc) * w2o;
    }
    __syncthreads();
    // tree-reduce over o for each r
    for (int s = 64; s > 0; s >>= 1) {
        if (o < s) {
#pragma unroll
            for (int r = 0; r < RR; r++) h[r][o] += h[r][o + s];
        }
        __syncthreads();
    }
    if (o < RR) {
        float z = h[o][0];
        g_alpha[o] = 1.0f / (1.0f + expf(-z));
    }
}

// ---------------------------------------------------------------------------
// Kernel 2: g_y[M,128] = ent_mat[M,128] @ weight_ent[128,128]  (fp32 SIMT)
// BM=128, BN=128(full), BK=8, 256 threads, 8x8 thread tiles.
// ---------------------------------------------------------------------------
__global__ __launch_bounds__(256) void gemm_kernel(const float* __restrict__ A,
                                                   const float* __restrict__ B,
                                                   float* __restrict__ C) {
    __shared__ float As[8][128];  // transposed: As[k][m]
    __shared__ float Bs[8][128];

    int tid = threadIdx.x;
    int row_t = tid >> 4;   // 0..15
    int col_t = tid & 15;   // 0..15
    int m0 = blockIdx.x * 128;

    float acc[8][8];
#pragma unroll
    for (int i = 0; i < 8; i++)
#pragma unroll
        for (int j = 0; j < 8; j++) acc[i][j] = 0.0f;

    int a_row = tid >> 1;        // 0..127
    int a_k4  = (tid & 1) * 4;   // 0 or 4
    int b_kk  = tid >> 5;        // 0..7
    int b_c4  = (tid & 31) * 4;  // 0,4,...,124

    for (int k0 = 0; k0 < 128; k0 += 8) {
        float4 av = make_float4(0.f, 0.f, 0.f, 0.f);
        int grow = m0 + a_row;
        if (grow < NN) av = *(const float4*)(A + (long)grow * FF + k0 + a_k4);
        As[a_k4 + 0][a_row] = av.x;
        As[a_k4 + 1][a_row] = av.y;
        As[a_k4 + 2][a_row] = av.z;
        As[a_k4 + 3][a_row] = av.w;
        *(float4*)(&Bs[b_kk][b_c4]) = *(const float4*)(B + (k0 + b_kk) * FF + b_c4);
        __syncthreads();
#pragma unroll
        for (int kk = 0; kk < 8; kk++) {
            float a[8], b[8];
            *(float4*)(a)     = *(const float4*)(&As[kk][row_t * 8]);
            *(float4*)(a + 4) = *(const float4*)(&As[kk][row_t * 8 + 4]);
            *(float4*)(b)     = *(const float4*)(&Bs[kk][col_t * 8]);
            *(float4*)(b + 4) = *(const float4*)(&Bs[kk][col_t * 8 + 4]);
#pragma unroll
            for (int i = 0; i < 8; i++)
#pragma unroll
                for (int j = 0; j < 8; j++) acc[i][j] += a[i] * b[j];
        }
        __syncthreads();
    }

#pragma unroll
    for (int i = 0; i < 8; i++) {
        int grow = m0 + row_t * 8 + i;
        if (grow < NN) {
            *(float4*)(C + (long)grow * FF + col_t * 8) =
                make_float4(acc[i][0], acc[i][1], acc[i][2], acc[i][3]);
            *(float4*)(C + (long)grow * FF + col_t * 8 + 4) =
                make_float4(acc[i][4], acc[i][5], acc[i][6], acc[i][7]);
        }
    }
}

// ---------------------------------------------------------------------------
// Kernel 3: zero the ent_output region of d_out, copy rel_mat into the tail.
// ---------------------------------------------------------------------------
__global__ void init_out_kernel(float* __restrict__ out,
                                const float* __restrict__ rel_mat) {
    int i = blockIdx.x * blockDim.x + threadIdx.x;
    const int n4 = NN * FF / 4;  // 1,280,000 float4s
    if (i < n4) {
        ((float4*)out)[i] = make_float4(0.f, 0.f, 0.f, 0.f);
    }
    if (i < RR * FF / 4) {  // 256 float4s
        ((float4*)(out + (long)NN * FF))[i] = ((const float4*)rel_mat)[i];
    }
}

// ---------------------------------------------------------------------------
// Kernel 4: edge scatter. One warp per edge:
//   out[src,:] += (alpha[r]*val) * y[dst,:]
// using vector reduction red.global.add.v4.f32 (16B per lane).
// ---------------------------------------------------------------------------
__global__ __launch_bounds__(256) void scatter_kernel(const float* __restrict__ edge_val,
                                                      const int* __restrict__ edge_src,
                                                      const int* __restrict__ edge_dst,
                                                      float* __restrict__ out) {
    int gwarp = (blockIdx.x * blockDim.x + threadIdx.x) >> 5;
    int lane = threadIdx.x & 31;
    if (gwarp >= NEDGES) return;

    int r = gwarp / EE;  // relation index (arrays are [R][E] contiguous -> flat index = gwarp)
    float coef = g_alpha[r] * __ldg(edge_val + gwarp);
    int src = __ldg(edge_src + gwarp);
    int dst = __ldg(edge_dst + gwarp);

    float4 v = ((const float4*)(g_y + (long)dst * FF))[lane];
    float4 m = make_float4(v.x * coef, v.y * coef, v.z * coef, v.w * coef);
    float* addr = out + (long)src * FF + lane * 4;
    asm volatile("red.global.add.v4.f32 [%0], {%1, %2, %3, %4};"
                 :: "l"(addr), "f"(m.x), "f"(m.y), "f"(m.z), "f"(m.w)
                 : "memory");
}

// ---------------------------------------------------------------------------
extern "C" void kernel_launch(void* const* d_in, const int* in_sizes, int n_in,
                              void* d_out, int out_size) {
    const float* ent_mat    = (const float*)d_in[0];
    const float* rel_mat    = (const float*)d_in[1];
    const int*   edge_src   = (const int*)d_in[2];
    const int*   edge_dst   = (const int*)d_in[3];
    const float* edge_val   = (const float*)d_in[4];
    const float* weight_ent = (const float*)d_in[5];
    const float* proj_w1    = (const float*)d_in[6];
    const float* proj_b1    = (const float*)d_in[7];
    const float* proj_w2    = (const float*)d_in[8];
    float* out = (float*)d_out;

    float* y;
    cudaGetSymbolAddress((void**)&y, g_y);

    // 1) alpha (tiny)
    alpha_kernel<<<1, 128>>>(rel_mat, proj_w1, proj_b1, proj_w2);

    // 2) y = ent_mat @ weight_ent
    gemm_kernel<<<(NN + 127) / 128, 256>>>(ent_mat, weight_ent, y);

    // 3) zero output + rel_mat tail (independent; stream-ordered before scatter)
    init_out_kernel<<<(NN * FF / 4 + 255) / 256, 256>>>(out, rel_mat);

    // 4) scatter: one warp per edge
    int warps_per_block = 256 / 32;
    int nblocks = (NEDGES + warps_per_block - 1) / warps_per_block;
    scatter_kernel<<<nblocks, 256>>>(edge_val, edge_src, edge_dst, out);
}